// round 14
// baseline (speedup 1.0000x reference)
#include <cuda_runtime.h>
#include <cuda_fp16.h>
#include <cstdint>

#define C_DIM  64
#define K_DIM  1024
#define HW     4096
#define NPOS   131072
#define MTILE  128
#define BTILE  64
#define NBT    16
#define NTHREADS 128
#define SLOTS  16
#define ZP     132
#define FINF   3.402823466e+38f

// ---------- static device scratch ----------
__device__ __align__(128) char g_ebuf[NBT * 16384];  // tile images [t][hi 8K|lo 8K] (hi used)
__device__ float    g_nrm[K_DIM];
__device__ unsigned g_maxE[2];                       // float-bits: max ||eh||, max ||elo_s||
__device__ __align__(16) uint4 g_rec[(size_t)NPOS * 4 * SLOTS];  // candidate records
__device__ unsigned g_cnt[NPOS * 4];
__device__ float    g_eps[NPOS];                     // per-position 2*eps' threshold add

// ---------- prep: norms + fp16 split + tile images + max split-norms ----------
__global__ void prep(const float* __restrict__ emb) {
    const int t = threadIdx.x;
    const int k = blockIdx.x * 64 + (t >> 2);
    const int q = t & 3;
    const float4* src = (const float4*)(emb + (size_t)k * C_DIM + q * 16);
    float4 v0 = src[0], v1 = src[1], v2 = src[2], v3 = src[3];
    float w[16] = { v0.x, v0.y, v0.z, v0.w, v1.x, v1.y, v1.z, v1.w,
                    v2.x, v2.y, v2.z, v2.w, v3.x, v3.y, v3.z, v3.w };

    float s = 0.f;
#pragma unroll
    for (int i = 0; i < 16; i++) s += w[i] * w[i];
    s += __shfl_xor_sync(0xFFFFFFFFu, s, 1);
    s += __shfl_xor_sync(0xFFFFFFFFu, s, 2);
    if (q == 0) g_nrm[k] = s;

    const int tt = k >> 6, n = k & 63;
    const int nt2 = n >> 4, rr = n & 15, slot = rr >> 3, r = rr & 7;
    char* base = g_ebuf + (size_t)tt * 16384 + nt2 * 2048 + r * 256
               + ((q ^ (r & 3)) * 64) + slot * 8;
    float seh = 0.f, sel = 0.f;
#pragma unroll
    for (int c0 = 0; c0 < 4; c0++) {
        float a0 = w[2 * c0], a1 = w[2 * c0 + 1], a2 = w[2 * c0 + 8], a3 = w[2 * c0 + 9];
        __half h0 = __float2half_rn(a0), h1 = __float2half_rn(a1);
        __half h2 = __float2half_rn(a2), h3 = __float2half_rn(a3);
        float f0 = __half2float(h0), f1 = __half2float(h1);
        float f2 = __half2float(h2), f3 = __half2float(h3);
        float r0 = (a0 - f0) * 2048.f, r1 = (a1 - f1) * 2048.f;
        float r2 = (a2 - f2) * 2048.f, r3 = (a3 - f3) * 2048.f;
        seh += f0 * f0 + f1 * f1 + f2 * f2 + f3 * f3;
        sel += r0 * r0 + r1 * r1 + r2 * r2 + r3 * r3;
        __half hv[4] = { h0, h1, h2, h3 };
        __half lv[4] = { __float2half_rn(r0), __float2half_rn(r1),
                         __float2half_rn(r2), __float2half_rn(r3) };
        *(uint64_t*)(base + c0 * 16)        = *(uint64_t*)hv;
        *(uint64_t*)(base + c0 * 16 + 8192) = *(uint64_t*)lv;
    }
    seh += __shfl_xor_sync(0xFFFFFFFFu, seh, 1);
    seh += __shfl_xor_sync(0xFFFFFFFFu, seh, 2);
    sel += __shfl_xor_sync(0xFFFFFFFFu, sel, 1);
    sel += __shfl_xor_sync(0xFFFFFFFFu, sel, 2);
    if (q == 0) {
        atomicMax(&g_maxE[0], __float_as_uint(sqrtf(seh)));
        atomicMax(&g_maxE[1], __float_as_uint(sqrtf(sel)));
    }
}

// ---------- mma + bulk-copy helpers ----------
__device__ __forceinline__ void mma16(float* d, uint4 a, uint32_t bx, uint32_t by) {
    asm volatile("mma.sync.aligned.m16n8k16.row.col.f32.f16.f16.f32 "
        "{%0,%1,%2,%3}, {%4,%5,%6,%7}, {%8,%9}, {%0,%1,%2,%3};"
        : "+f"(d[0]), "+f"(d[1]), "+f"(d[2]), "+f"(d[3])
        : "r"(a.x), "r"(a.z), "r"(a.y), "r"(a.w), "r"(bx), "r"(by));
}
__device__ __forceinline__ uint32_t smem_u32(const void* p) {
    uint32_t a;
    asm("{ .reg .u64 t; cvta.to.shared.u64 t, %1; cvt.u32.u64 %0, t; }" : "=r"(a) : "l"(p));
    return a;
}
#define MBAR_INIT(addr, cnt) \
    asm volatile("mbarrier.init.shared.b64 [%0], %1;" :: "r"(addr), "r"(cnt) : "memory")
#define MBAR_EXPECT_TX(addr, bytes) \
    asm volatile("mbarrier.arrive.expect_tx.shared.b64 _, [%0], %1;" \
                 :: "r"(addr), "r"((uint32_t)(bytes)) : "memory")
#define MBAR_WAIT(addr, ph) do {                                               \
    uint32_t _a = (addr), _p = (ph), _d;                                       \
    asm volatile("{\n\t.reg .pred p;\n\t"                                      \
        "mbarrier.try_wait.parity.acquire.cta.shared::cta.b64 p, [%1], %2;\n\t"\
        "selp.b32 %0, 1, 0, p;\n\t}"                                           \
        : "=r"(_d) : "r"(_a), "r"(_p) : "memory");                             \
    while (!_d) {                                                              \
        asm volatile("{\n\t.reg .pred p;\n\t"                                  \
            "mbarrier.try_wait.parity.acquire.cta.shared::cta.b64 p, [%1], %2, 0x989680;\n\t" \
            "selp.b32 %0, 1, 0, p;\n\t}"                                       \
            : "=r"(_d) : "r"(_a), "r"(_p) : "memory");                         \
    }                                                                          \
} while (0)
__device__ __forceinline__ void bulk_copy8k(uint32_t dst_smem, const void* src, uint32_t mbar) {
    asm volatile("cp.async.bulk.shared::cluster.global.mbarrier::complete_tx::bytes "
                 "[%0], [%1], %2, [%3];"
                 :: "r"(dst_smem), "l"(src), "r"(8192u), "r"(mbar) : "memory");
}

// smem: bufs 3 x 8KB at [0,24576); ztr (64 x 132 f32 = 33792B) overlays [0,33792) at
// startup; norms at 33792 (4KB); mbars at 37888
#define SM_NRM  33792
#define SM_MBAR 37888
#define SM_TOT  37952

__device__ __forceinline__ uint32_t packh2(float a, float b) {
    __half2 h = __floats2half2_rn(a, b);
    return *(uint32_t*)&h;
}

// build hi A-fragments for base row pa; also output hi/lo norm² partials (this lane's dims)
__device__ __forceinline__ void build_frag_h(const float* ztr, int pa, int c0, uint4* Ah,
                                             float* sh_a, float* sl_a, float* sh_b, float* sl_b) {
    const int pb = pa + 8;
    float sha = 0.f, sla = 0.f, shb = 0.f, slb = 0.f;
#pragma unroll
    for (int ks = 0; ks < 4; ks++) {
        int k0 = 16 * ks + 2 * c0;
        float v0 = ztr[(k0    ) * ZP + pa], v1 = ztr[(k0 + 1) * ZP + pa];
        float v2 = ztr[(k0 + 8) * ZP + pa], v3 = ztr[(k0 + 9) * ZP + pa];
        float v4 = ztr[(k0    ) * ZP + pb], v5 = ztr[(k0 + 1) * ZP + pb];
        float v6 = ztr[(k0 + 8) * ZP + pb], v7 = ztr[(k0 + 9) * ZP + pb];
        float h0 = __half2float(__float2half_rn(v0));
        float h1 = __half2float(__float2half_rn(v1));
        float h2 = __half2float(__float2half_rn(v2));
        float h3 = __half2float(__float2half_rn(v3));
        float h4 = __half2float(__float2half_rn(v4));
        float h5 = __half2float(__float2half_rn(v5));
        float h6 = __half2float(__float2half_rn(v6));
        float h7 = __half2float(__float2half_rn(v7));
        Ah[ks].x = packh2(h0, h1); Ah[ks].y = packh2(h2, h3);
        Ah[ks].z = packh2(h4, h5); Ah[ks].w = packh2(h6, h7);
        float r0 = (v0 - h0) * 2048.f, r1 = (v1 - h1) * 2048.f;
        float r2 = (v2 - h2) * 2048.f, r3 = (v3 - h3) * 2048.f;
        float r4 = (v4 - h4) * 2048.f, r5 = (v5 - h5) * 2048.f;
        float r6 = (v6 - h6) * 2048.f, r7 = (v7 - h7) * 2048.f;
        sha += h0 * h0 + h1 * h1 + h2 * h2 + h3 * h3;
        shb += h4 * h4 + h5 * h5 + h6 * h6 + h7 * h7;
        sla += r0 * r0 + r1 * r1 + r2 * r2 + r3 * r3;
        slb += r4 * r4 + r5 * r5 + r6 * r6 + r7 * r7;
    }
    *sh_a = sha; *sl_a = sla; *sh_b = shb; *sl_b = slb;
}

// ---------- pass 1: hh-only mma + certified candidate collection ----------
__global__ __launch_bounds__(NTHREADS, 4)
void vq_pass1(const float* __restrict__ z_e)
{
    extern __shared__ char smem[];
    float* nsm = (float*)(smem + SM_NRM);
    float* ztr = (float*)smem;                     // startup only

    const uint32_t sbm = smem_u32(smem);
    const uint32_t mb  = sbm + SM_MBAR;

    const int tid  = threadIdx.x;
    const int lane = tid & 31, warp = tid >> 5;
    const int c0   = lane & 3, r = lane >> 2;
    const int p0   = blockIdx.x * MTILE;
    const int b    = p0 >> 12, hw0 = p0 & (HW - 1);
    const int s    = blockIdx.x & 15;

    if (tid == 0) { MBAR_INIT(mb + 0, 1); MBAR_INIT(mb + 8, 1); MBAR_INIT(mb + 16, 1); }

    // norms -> smem
    ((float4*)nsm)[tid]            = ((const float4*)g_nrm)[tid];
    ((float4*)nsm)[tid + NTHREADS] = ((const float4*)g_nrm)[tid + NTHREADS];

    // z slab transpose
    {
        const float* zsrc = z_e + (size_t)b * C_DIM * HW + hw0;
#pragma unroll
        for (int i = 0; i < 16; i++) {
            int idx = tid + i * NTHREADS;
            int c = idx >> 5, x4 = idx & 31;
            float4 v = *(const float4*)(zsrc + (size_t)c * HW + x4 * 4);
            v.x *= -2.f; v.y *= -2.f; v.z *= -2.f; v.w *= -2.f;
            *(float4*)(ztr + c * ZP + x4 * 4) = v;
        }
    }
    __syncthreads();

    // A fragments (hi only) + split-norm partials
    uint4 AhA[4], AhB[4];
    float shA_a, slA_a, shA_b, slA_b, shB_a, slB_a, shB_b, slB_b;
    build_frag_h(ztr, warp * 16 + r,      c0, AhA, &shA_a, &slA_a, &shA_b, &slA_b);
    build_frag_h(ztr, 64 + warp * 16 + r, c0, AhB, &shB_a, &slB_a, &shB_b, &slB_b);
    // full 64-dim sums across the 4 c0-lanes
#pragma unroll
    for (int off = 1; off <= 2; off <<= 1) {
        shA_a += __shfl_xor_sync(0xFFFFFFFFu, shA_a, off);
        slA_a += __shfl_xor_sync(0xFFFFFFFFu, slA_a, off);
        shA_b += __shfl_xor_sync(0xFFFFFFFFu, shA_b, off);
        slA_b += __shfl_xor_sync(0xFFFFFFFFu, slA_b, off);
        shB_a += __shfl_xor_sync(0xFFFFFFFFu, shB_a, off);
        slB_a += __shfl_xor_sync(0xFFFFFFFFu, slB_a, off);
        shB_b += __shfl_xor_sync(0xFFFFFFFFu, shB_b, off);
        slB_b += __shfl_xor_sync(0xFFFFFFFFu, slB_b, off);
    }
    const float mEh  = __uint_as_float(g_maxE[0]);
    const float mElo = __uint_as_float(g_maxE[1]);
    float two[4];
    two[0] = 2.02f * ldexpf(sqrtf(shA_a) * mElo + sqrtf(slA_a) * mEh, -11) + 3e-3f;
    two[1] = 2.02f * ldexpf(sqrtf(shA_b) * mElo + sqrtf(slA_b) * mEh, -11) + 3e-3f;
    two[2] = 2.02f * ldexpf(sqrtf(shB_a) * mElo + sqrtf(slB_a) * mEh, -11) + 3e-3f;
    two[3] = 2.02f * ldexpf(sqrtf(shB_b) * mElo + sqrtf(slB_b) * mEh, -11) + 3e-3f;

    const int posn[4] = { p0 + warp * 16 + r,      p0 + warp * 16 + r + 8,
                          p0 + 64 + warp * 16 + r, p0 + 64 + warp * 16 + r + 8 };
    if (c0 == 0) {
        g_eps[posn[0]] = two[0]; g_eps[posn[1]] = two[1];
        g_eps[posn[2]] = two[2]; g_eps[posn[3]] = two[3];
    }
    size_t sbase[4];
#pragma unroll
    for (int i = 0; i < 4; i++) sbase[i] = ((size_t)posn[i] * 4 + c0) * SLOTS;

    __syncthreads();                               // ztr dead; bufs free; mbars visible

    if (tid == 0) {
        MBAR_EXPECT_TX(mb + 0, 8192);
        bulk_copy8k(sbm, g_ebuf + (size_t)s * 16384, mb + 0);
        MBAR_EXPECT_TX(mb + 8, 8192);
        bulk_copy8k(sbm + 8192, g_ebuf + (size_t)((s + 1) & 15) * 16384, mb + 8);
    }

    int kk[4];
#pragma unroll
    for (int ks = 0; ks < 4; ks++) kk[ks] = ((ks ^ (r & 3)) * 64) + c0 * 16;

    float    best[4] = { FINF, FINF, FINF, FINF };
    unsigned cnt[4]  = { 0, 0, 0, 0 };

#define COLLECT(d0, d1, kb, i) do {                                            \
    float _m = fminf(d0, d1);                                                  \
    if (_m < best[i] + two[i]) {                                               \
        if (cnt[i] < SLOTS) {                                                  \
            uint4 _rec;                                                        \
            _rec.x = __float_as_uint(d0); _rec.y = __float_as_uint(d1);        \
            _rec.z = (unsigned)(kb);      _rec.w = 0u;                         \
            g_rec[sbase[i] + cnt[i]] = _rec;                                   \
        }                                                                      \
        cnt[i]++;                                                              \
    }                                                                          \
    best[i] = fminf(best[i], _m);                                              \
} while (0)

    for (int j = 0; j < NBT; j++) {
        const int bufid = j % 3;
        MBAR_WAIT(mb + bufid * 8, (j / 3) & 1);
        __syncthreads();
        if (tid == 0 && j + 2 < NBT) {
            int nb = (j + 2) % 3;
            MBAR_EXPECT_TX(mb + nb * 8, 8192);
            bulk_copy8k(sbm + (uint32_t)nb * 8192,
                        g_ebuf + (size_t)((s + j + 2) & 15) * 16384, mb + nb * 8);
        }

        const int  tact = (s + j) & 15;
        const char* buf = smem + (size_t)bufid * 8192;

#pragma unroll
        for (int nt2 = 0; nt2 < 4; nt2++) {
            const int  n0 = tact * BTILE + nt2 * 16;
            const char* bA = buf + nt2 * 2048 + r * 256;

            float2 nv0 = *(const float2*)(nsm + n0 + 2 * c0);
            float2 nv1 = *(const float2*)(nsm + n0 + 8 + 2 * c0);
            float hA0[4] = { nv0.x, nv0.y, nv0.x, nv0.y };
            float hA1[4] = { nv1.x, nv1.y, nv1.x, nv1.y };
            float hB0[4] = { nv0.x, nv0.y, nv0.x, nv0.y };
            float hB1[4] = { nv1.x, nv1.y, nv1.x, nv1.y };

#pragma unroll
            for (int ks = 0; ks < 4; ks++) {
                uint4 bh = *(const uint4*)(bA + kk[ks]);
                mma16(hA0, AhA[ks], bh.x, bh.y);
                mma16(hA1, AhA[ks], bh.z, bh.w);
                mma16(hB0, AhB[ks], bh.x, bh.y);
                mma16(hB1, AhB[ks], bh.z, bh.w);
            }

            const int kb0 = n0 + 2 * c0, kb1 = n0 + 8 + 2 * c0;
            COLLECT(hA0[0], hA0[1], kb0, 0);
            COLLECT(hA1[0], hA1[1], kb1, 0);
            COLLECT(hA0[2], hA0[3], kb0, 1);
            COLLECT(hA1[2], hA1[3], kb1, 1);
            COLLECT(hB0[0], hB0[1], kb0, 2);
            COLLECT(hB1[0], hB1[1], kb1, 2);
            COLLECT(hB0[2], hB0[3], kb0, 3);
            COLLECT(hB1[2], hB1[3], kb1, 3);
        }
    }
#undef COLLECT

#pragma unroll
    for (int i = 0; i < 4; i++) g_cnt[posn[i] * 4 + c0] = cnt[i];
}

// ---------- pass 2: filter + exact fp32 rescore + gather ----------
__device__ __forceinline__ float score64(const float* __restrict__ emb,
                                         const float* v, int k) {
    const float4* e4 = (const float4*)(emb + (size_t)k * C_DIM);
    float s0 = 0.f, s1 = 0.f, s2 = 0.f, s3 = 0.f;
#pragma unroll
    for (int i = 0; i < 16; i++) {
        float4 e = e4[i];
        s0 = fmaf(v[4 * i + 0], e.x, s0);
        s1 = fmaf(v[4 * i + 1], e.y, s1);
        s2 = fmaf(v[4 * i + 2], e.z, s2);
        s3 = fmaf(v[4 * i + 3], e.w, s3);
    }
    return g_nrm[k] + ((s0 + s1) + (s2 + s3));
}

__global__ __launch_bounds__(256)
void vq_pass2(const float* __restrict__ z_e, const float* __restrict__ emb,
              float* __restrict__ out)
{
    const int p  = blockIdx.x * 256 + threadIdx.x;
    const int b  = p >> 12, hw = p & (HW - 1);

    float v[64];
    const float* zs = z_e + (size_t)b * C_DIM * HW + hw;
#pragma unroll
    for (int c = 0; c < 64; c++) v[c] = -2.f * zs[(size_t)c * HW];

    unsigned c4[4];
    bool over = false;
#pragma unroll
    for (int i = 0; i < 4; i++) { c4[i] = g_cnt[p * 4 + i]; over |= (c4[i] > SLOTS); }

    float bestv = FINF; int bestk = 0;
    if (!over) {
        float bh = FINF;
        for (int i = 0; i < 4; i++) {
            const uint4* rs = &g_rec[((size_t)p * 4 + i) * SLOTS];
            for (unsigned j = 0; j < c4[i]; j++) {
                uint4 rec = rs[j];
                bh = fminf(bh, fminf(__uint_as_float(rec.x), __uint_as_float(rec.y)));
            }
        }
        const float thr = bh + g_eps[p];
        for (int i = 0; i < 4; i++) {
            const uint4* rs = &g_rec[((size_t)p * 4 + i) * SLOTS];
            for (unsigned j = 0; j < c4[i]; j++) {
                uint4 rec = rs[j];
                float d0 = __uint_as_float(rec.x), d1 = __uint_as_float(rec.y);
                int   kb = (int)rec.z;
                if (d0 < thr) {
                    float d = score64(emb, v, kb);
                    if (d < bestv || (d == bestv && kb < bestk)) { bestv = d; bestk = kb; }
                }
                if (d1 < thr) {
                    float d = score64(emb, v, kb + 1);
                    if (d < bestv || (d == bestv && kb + 1 < bestk)) { bestv = d; bestk = kb + 1; }
                }
            }
        }
    } else {
        for (int k = 0; k < K_DIM; k++) {
            float d = score64(emb, v, k);
            if (d < bestv) { bestv = d; bestk = k; }   // ascending k: strict < = smallest-k tie
        }
    }

    // gather winner row, scatter to [B, C, H, W] (coalesced across threads per c)
    const float4* ev = (const float4*)(emb + (size_t)bestk * C_DIM);
    float* op = out + (size_t)b * C_DIM * HW + hw;
#pragma unroll
    for (int c4i = 0; c4i < 16; c4i++) {
        float4 e = ev[c4i];
        op[(size_t)(c4i * 4 + 0) * HW] = e.x;
        op[(size_t)(c4i * 4 + 1) * HW] = e.y;
        op[(size_t)(c4i * 4 + 2) * HW] = e.z;
        op[(size_t)(c4i * 4 + 3) * HW] = e.w;
    }
}

// ---------- launch ----------
extern "C" void kernel_launch(void* const* d_in, const int* in_sizes, int n_in,
                              void* d_out, int out_size)
{
    const float* z_e = (const float*)d_in[0];   // [32, 64, 64, 64]
    const float* emb = (const float*)d_in[1];   // [1024, 64]
    float*       out = (float*)d_out;

    cudaFuncSetAttribute(vq_pass1, cudaFuncAttributeMaxDynamicSharedMemorySize, SM_TOT);

    prep<<<K_DIM / 64, 256>>>(emb);
    vq_pass1<<<NPOS / MTILE, NTHREADS, SM_TOT>>>(z_e);
    vq_pass2<<<NPOS / 256, 256>>>(z_e, emb, out);
}